// round 9
// baseline (speedup 1.0000x reference)
#include <cuda_runtime.h>

#define TI 128          /* i-extent per block */
#define TJ 32           /* j-extent per block */
#define NT 256
#define MAX_TILES 64
#define MAX_B (MAX_TILES * (MAX_TILES + 1) * 2)

__device__ double       g_part[MAX_B];
__device__ unsigned int g_count;   // zero at load; last block resets each launch

// SIGMA=1 -> a=1/sqrt(2), c=2a/sqrt(pi).  KEXP = -0.5*log2(e)
#define C_CONST   0.79788456080286536f
#define PA_CONST  0.23174530376899319f   /* 0.3275911 * a */
#define KEXP     -0.72134752044448170f

typedef unsigned long long u64;
struct F2 { u64 v; };

__device__ __forceinline__ F2 pack2(float lo, float hi) {
    F2 r; asm("mov.b64 %0,{%1,%2};" : "=l"(r.v) : "f"(lo), "f"(hi)); return r;
}
__device__ __forceinline__ void unpack2(F2 a, float& lo, float& hi) {
    asm("mov.b64 {%0,%1},%2;" : "=f"(lo), "=f"(hi) : "l"(a.v));
}
__device__ __forceinline__ F2 add2(F2 a, F2 b) {
    F2 r; asm("add.rn.f32x2 %0,%1,%2;" : "=l"(r.v) : "l"(a.v), "l"(b.v)); return r;
}
__device__ __forceinline__ F2 mul2(F2 a, F2 b) {
    F2 r; asm("mul.rn.f32x2 %0,%1,%2;" : "=l"(r.v) : "l"(a.v), "l"(b.v)); return r;
}
__device__ __forceinline__ F2 fma2(F2 a, F2 b, F2 c) {
    F2 r; asm("fma.rn.f32x2 %0,%1,%2,%3;" : "=l"(r.v) : "l"(a.v), "l"(b.v), "l"(c.v)); return r;
}
__device__ __forceinline__ float ex2f(float x)  { float r; asm("ex2.approx.f32 %0,%1;"   : "=f"(r) : "f"(x)); return r; }
__device__ __forceinline__ float rcpf(float x)  { float r; asm("rcp.approx.f32 %0,%1;"   : "=f"(r) : "f"(x)); return r; }
__device__ __forceinline__ float rsqf(float x)  { float r; asm("rsqrt.approx.f32 %0,%1;" : "=f"(r) : "f"(x)); return r; }

// scalar erf tail (A&S 7.1.26); same ops as correction path -> exact cancellation
__device__ __forceinline__ float erf_part(float rsq, float rinv, float gauss) {
    float rr = rsq * rinv;
    float t  = rcpf(fmaf(PA_CONST, rr, 1.0f));
    float poly = fmaf(t, fmaf(t, fmaf(t, fmaf(t, 1.061405429f, -1.453152027f),
                                      1.421413741f), -0.284496736f), 0.254829592f);
    return fmaf(-(t * poly), gauss, 1.0f);
}

struct IPack { F2 nx, ny, nz, ux, uy, uz, q, nq; };

template<bool DIAG>
__device__ __forceinline__ F2 chain(const IPack& ip,
    F2 xj, F2 yj, F2 zj, F2 qj, F2 uxj, F2 uyj, F2 uzj,
    F2 NEGC2, F2 TWO2, F2 NEG12)
{
    F2 dx = add2(xj, ip.nx);
    F2 dy = add2(yj, ip.ny);
    F2 dz = add2(zj, ip.nz);
    F2 rsqp = fma2(dx, dx, fma2(dy, dy, mul2(dz, dz)));

    float r0, r1; unpack2(rsqp, r0, r1);
    if (DIAG) {
        r0 = (r0 == 0.0f) ? 1.0f : r0;   // self pair; corrected analytically later
        r1 = (r1 == 0.0f) ? 1.0f : r1;
    }
    float rinv0 = rsqf(r0),        rinv1 = rsqf(r1);
    float g0    = ex2f(r0 * KEXP), g1    = ex2f(r1 * KEXP);
    float e0    = erf_part(r0, rinv0, g0);
    float e1s   = erf_part(r1, rinv1, g1);

    F2 rinvp  = pack2(rinv0, rinv1);
    F2 gaussp = pack2(g0, g1);
    F2 erfp   = pack2(e0, e1s);

    F2 rinv2p = mul2(rinvp, rinvp);
    F2 e1p    = mul2(erfp, rinvp);
    F2 e3p    = mul2(e1p, rinv2p);
    F2 ncgp   = mul2(gaussp, NEGC2);         // -c*gauss
    F2 s1p    = fma2(ncgp, rinv2p, e3p);     // e3 - c*gauss/r^2
    F2 epn    = add2(e3p, ncgp);
    F2 s2p    = fma2(s1p, TWO2, epn);        // 2*s1 + e3 - c*gauss

    F2 udip = fma2(ip.ux, dx, fma2(ip.uy, dy, mul2(ip.uz, dz)));
    F2 udjp = fma2(uxj,   dx, fma2(uyj,   dy, mul2(uzj,   dz)));
    F2 uup  = fma2(ip.ux, uxj, fma2(ip.uy, uyj, mul2(ip.uz, uzj)));

    F2 prp  = mul2(mul2(qj, ip.q), e1p);                 // qq
    F2 inn  = fma2(qj, udip, mul2(ip.nq, udjp));         // qj*udi - qi*udj
    F2 ns1p = mul2(s1p, NEG12);
    prp = fma2(ns1p, inn, prp);                          // qu
    prp = fma2(s1p, uup, prp);                           // uu iso
    F2 m2   = mul2(mul2(udip, udjp), rinv2p);
    F2 ns2p = mul2(s2p, NEG12);
    prp = fma2(ns2p, m2, prp);                           // uu aniso
    return prp;
}

// self-term computed with EXACTLY the same approx op sequence (rsq=1, d=0)
__device__ __forceinline__ float self_term(float qi, float uix, float uiy, float uiz) {
    float rinvS  = rsqf(1.0f);
    float gS     = ex2f(1.0f * KEXP);
    float eS     = erf_part(1.0f, rinvS, gS);
    float rinv2S = rinvS * rinvS;
    float e1S    = eS * rinvS;
    float e3S    = e1S * rinv2S;
    float ncgS   = gS * (-C_CONST);
    float s1S    = fmaf(ncgS, rinv2S, e3S);
    float uu_i   = fmaf(uix, uix, fmaf(uiy, uiy, uiz * uiz));
    return (qi * qi) * e1S + s1S * uu_i;
}

template<bool DIAG>
__device__ __forceinline__ double block_accum(
    const IPack& ipA, const IPack& ipB,
    const u64* sx2, const u64* sy2, const u64* sz2, const u64* sq2,
    const u64* sux2, const u64* suy2, const u64* suz2,
    int jg, F2 NEGC2, F2 TWO2, F2 NEG12)
{
    F2 facc; facc.v = 0ull;
    #pragma unroll
    for (int k = 0; k < 4; k++) {
        const int lp = jg * 4 + k;           // u64 slot; covers j offsets 2lp, 2lp+1
        F2 xj, yj, zj, qj, uxj, uyj, uzj;
        xj.v  = sx2[lp];  yj.v  = sy2[lp];  zj.v  = sz2[lp]; qj.v = sq2[lp];
        uxj.v = sux2[lp]; uyj.v = suy2[lp]; uzj.v = suz2[lp];

        facc = add2(facc, chain<DIAG>(ipA, xj, yj, zj, qj, uxj, uyj, uzj, NEGC2, TWO2, NEG12));
        facc = add2(facc, chain<DIAG>(ipB, xj, yj, zj, qj, uxj, uyj, uzj, NEGC2, TWO2, NEG12));
    }
    float f0, f1; unpack2(facc, f0, f1);
    return (double)(f0 + f1);
}

__global__ void __launch_bounds__(NT, 3) pair_kernel(
    const float* __restrict__ q, const float* __restrict__ r,
    const float* __restrict__ u, int n, int tiles, float outscale,
    float* __restrict__ out)
{
    // ---- block -> (tile-pair, j-quarter) ----
    int p4 = blockIdx.x;
    int pr = p4 >> 2;
    const int jh = p4 & 3;
    int bi = 0;
    while (pr >= tiles - bi) { pr -= tiles - bi; bi++; }
    const int bj = bi + pr;
    const bool diag = (bi == bj);

    __shared__ __align__(16) float s_x[TJ], s_y[TJ], s_z[TJ], s_q[TJ];
    __shared__ __align__(16) float s_ux[TJ], s_uy[TJ], s_uz[TJ];

    const int tx = threadIdx.x;
    const int il = tx & 63;           // i-lane 0..63 ; thread owns i1=il, i2=il+64
    const int jg = tx >> 6;           // j-group 0..3 (8 j's each)
    const int i1 = bi * TI + il;
    const int i2 = i1 + 64;
    const int j0 = bj * TI + jh * TJ;

    if (tx < TJ) {
        int j = j0 + tx;
        if (j < n) { s_x[tx] = r[3*j]; s_y[tx] = r[3*j+1]; s_z[tx] = r[3*j+2]; s_q[tx] = q[j]; }
        else       { s_x[tx] = 1.0e7f + (float)j; s_y[tx] = 0.f; s_z[tx] = 0.f; s_q[tx] = 0.f; }
    } else if (tx < 2 * TJ) {
        int jt = tx - TJ, j = j0 + jt;
        if (j < n) { s_ux[jt] = u[3*j]; s_uy[jt] = u[3*j+1]; s_uz[jt] = u[3*j+2]; }
        else       { s_ux[jt] = 0.f; s_uy[jt] = 0.f; s_uz[jt] = 0.f; }
    }

    float q1 = 0.f, x1, y1 = 0.f, z1 = 0.f, ux1 = 0.f, uy1 = 0.f, uz1 = 0.f;
    float q2v = 0.f, x2, y2 = 0.f, z2 = 0.f, ux2v = 0.f, uy2v = 0.f, uz2v = 0.f;
    if (i1 < n) {
        q1 = q[i1]; x1 = r[3*i1]; y1 = r[3*i1+1]; z1 = r[3*i1+2];
        ux1 = u[3*i1]; uy1 = u[3*i1+1]; uz1 = u[3*i1+2];
    } else { x1 = 2.0e7f + (float)i1; }
    if (i2 < n) {
        q2v = q[i2]; x2 = r[3*i2]; y2 = r[3*i2+1]; z2 = r[3*i2+2];
        ux2v = u[3*i2]; uy2v = u[3*i2+1]; uz2v = u[3*i2+2];
    } else { x2 = 3.0e7f + (float)i2; }
    __syncthreads();

    IPack ipA, ipB;
    ipA.nx = pack2(-x1, -x1); ipA.ny = pack2(-y1, -y1); ipA.nz = pack2(-z1, -z1);
    ipA.ux = pack2(ux1, ux1); ipA.uy = pack2(uy1, uy1); ipA.uz = pack2(uz1, uz1);
    ipA.q  = pack2(q1, q1);   ipA.nq = pack2(-q1, -q1);
    ipB.nx = pack2(-x2, -x2); ipB.ny = pack2(-y2, -y2); ipB.nz = pack2(-z2, -z2);
    ipB.ux = pack2(ux2v, ux2v); ipB.uy = pack2(uy2v, uy2v); ipB.uz = pack2(uz2v, uz2v);
    ipB.q  = pack2(q2v, q2v);   ipB.nq = pack2(-q2v, -q2v);

    const F2 NEGC2 = pack2(-C_CONST, -C_CONST);
    const F2 TWO2  = pack2(2.0f, 2.0f);
    const F2 NEG12 = pack2(-1.0f, -1.0f);

    const u64* sx2  = reinterpret_cast<const u64*>(s_x);
    const u64* sy2  = reinterpret_cast<const u64*>(s_y);
    const u64* sz2  = reinterpret_cast<const u64*>(s_z);
    const u64* sq2  = reinterpret_cast<const u64*>(s_q);
    const u64* sux2 = reinterpret_cast<const u64*>(s_ux);
    const u64* suy2 = reinterpret_cast<const u64*>(s_uy);
    const u64* suz2 = reinterpret_cast<const u64*>(s_uz);

    double acc;
    if (!diag) {
        acc = block_accum<false>(ipA, ipB, sx2, sy2, sz2, sq2, sux2, suy2, suz2,
                                 jg, NEGC2, TWO2, NEG12);
    } else {
        acc = block_accum<true>(ipA, ipB, sx2, sy2, sz2, sq2, sux2, suy2, suz2,
                                jg, NEGC2, TWO2, NEG12);
        // subtract fake self-pair terms (this thread's j-window = [jh*32+8jg, +8))
        const int w0 = jh * TJ + 8 * jg;
        if ((unsigned)(il - w0) < 8u)
            acc -= (double)self_term(q1, ux1, uy1, uz1);
        if ((unsigned)(il + 64 - w0) < 8u)
            acc -= (double)self_term(q2v, ux2v, uy2v, uz2v);
        acc *= 0.5;   // diagonal tile double-counts each unordered pair
    }

    // ---- deterministic block reduction ----
    #pragma unroll
    for (int off = 16; off > 0; off >>= 1)
        acc += __shfl_down_sync(0xffffffffu, acc, off);

    __shared__ double warp_s[NT / 32];
    if ((tx & 31) == 0) warp_s[tx >> 5] = acc;
    __syncthreads();

    __shared__ bool isLast;
    if (tx == 0) {
        double s = 0.0;
        #pragma unroll
        for (int w = 0; w < NT / 32; w++) s += warp_s[w];
        g_part[blockIdx.x] = s;
        __threadfence();
        unsigned c = atomicAdd(&g_count, 1u);
        isLast = (c == gridDim.x - 1);
    }
    __syncthreads();

    // ---- last block: final reduction (fixed order -> deterministic) ----
    if (isLast) {
        __threadfence();
        const int nB = gridDim.x;
        double s = 0.0;
        for (int k = tx; k < nB; k += NT) s += g_part[k];

        #pragma unroll
        for (int off = 16; off > 0; off >>= 1)
            s += __shfl_down_sync(0xffffffffu, s, off);

        __shared__ double fin_s[NT / 32];
        if ((tx & 31) == 0) fin_s[tx >> 5] = s;
        __syncthreads();
        if (tx == 0) {
            double tot = 0.0;
            #pragma unroll
            for (int w = 0; w < NT / 32; w++) tot += fin_s[w];
            out[0] = (float)(tot * (double)outscale);
            g_count = 0;   // reset for next graph replay
        }
    }
}

extern "C" void kernel_launch(void* const* d_in, const int* in_sizes, int n_in,
                              void* d_out, int out_size)
{
    const float* q = (const float*)d_in[0];
    const float* r = (const float*)d_in[1];
    const float* u = (const float*)d_in[2];
    float* out = (float*)d_out;

    int n = in_sizes[0];
    int tiles = (n + TI - 1) / TI;
    if (tiles > MAX_TILES) tiles = MAX_TILES;

    int nB = tiles * (tiles + 1) * 2;   // 4 j-quarter blocks per triangular tile-pair
    float outscale = (float)(90.0474 / 6.283185307179586476925286766559);

    pair_kernel<<<nB, NT>>>(q, r, u, n, tiles, outscale, out);
}

// round 10
// speedup vs baseline: 1.0021x; 1.0021x over previous
#include <cuda_runtime.h>

#define TI 128          /* i-extent per block */
#define TJ 32           /* j-extent per block */
#define NT 256
#define MAX_TILES 64
#define MAX_B (MAX_TILES * (MAX_TILES + 1) * 2)

__device__ double       g_part[MAX_B];
__device__ unsigned int g_count;   // zero at load; last block resets each launch

// SIGMA=1 -> a=1/sqrt(2), c=2a/sqrt(pi).  KEXP = -0.5*log2(e)
#define C_CONST   0.79788456080286536f
#define PA_CONST  0.23174530376899319f   /* 0.3275911 * a */
#define KEXP     -0.72134752044448170f

typedef unsigned long long u64;
struct F2 { u64 v; };

__device__ __forceinline__ F2 pack2(float lo, float hi) {
    F2 r; asm("mov.b64 %0,{%1,%2};" : "=l"(r.v) : "f"(lo), "f"(hi)); return r;
}
__device__ __forceinline__ void unpack2(F2 a, float& lo, float& hi) {
    asm("mov.b64 {%0,%1},%2;" : "=f"(lo), "=f"(hi) : "l"(a.v));
}
__device__ __forceinline__ F2 add2(F2 a, F2 b) {
    F2 r; asm("add.rn.f32x2 %0,%1,%2;" : "=l"(r.v) : "l"(a.v), "l"(b.v)); return r;
}
__device__ __forceinline__ F2 mul2(F2 a, F2 b) {
    F2 r; asm("mul.rn.f32x2 %0,%1,%2;" : "=l"(r.v) : "l"(a.v), "l"(b.v)); return r;
}
__device__ __forceinline__ F2 fma2(F2 a, F2 b, F2 c) {
    F2 r; asm("fma.rn.f32x2 %0,%1,%2,%3;" : "=l"(r.v) : "l"(a.v), "l"(b.v), "l"(c.v)); return r;
}
__device__ __forceinline__ float ex2f(float x)  { float r; asm("ex2.approx.f32 %0,%1;"   : "=f"(r) : "f"(x)); return r; }
__device__ __forceinline__ float rcpf(float x)  { float r; asm("rcp.approx.f32 %0,%1;"   : "=f"(r) : "f"(x)); return r; }
__device__ __forceinline__ float rsqf(float x)  { float r; asm("rsqrt.approx.f32 %0,%1;" : "=f"(r) : "f"(x)); return r; }

// scalar erf tail (A&S 7.1.26); same ops as correction path -> exact cancellation
__device__ __forceinline__ float erf_part(float rsq, float rinv, float gauss) {
    float rr = rsq * rinv;
    float t  = rcpf(fmaf(PA_CONST, rr, 1.0f));
    float poly = fmaf(t, fmaf(t, fmaf(t, fmaf(t, 1.061405429f, -1.453152027f),
                                      1.421413741f), -0.284496736f), 0.254829592f);
    return fmaf(-(t * poly), gauss, 1.0f);
}

// self-term computed with EXACTLY the same approx op sequence (rsq=1, d=0)
__device__ __forceinline__ float self_term(float qi, float uix, float uiy, float uiz) {
    float rinvS  = rsqf(1.0f);
    float gS     = ex2f(1.0f * KEXP);
    float eS     = erf_part(1.0f, rinvS, gS);
    float rinv2S = rinvS * rinvS;
    float e1S    = eS * rinvS;
    float e3S    = e1S * rinv2S;
    float ncgS   = gS * (-C_CONST);
    float s1S    = fmaf(ncgS, rinv2S, e3S);
    float uu_i   = fmaf(uix, uix, fmaf(uiy, uiy, uiz * uiz));
    return (qi * qi) * e1S + s1S * uu_i;
}

template<bool DIAG>
__device__ __forceinline__ double block_accum(
    F2 nx, F2 ny, F2 nz, F2 ux, F2 uy, F2 uz, F2 qq, F2 nq,
    const u64* sx2, const u64* sy2, const u64* sz2, const u64* sq2,
    const u64* sux2, const u64* suy2, const u64* suz2,
    int lp0, F2 NEGC2, F2 TWO2, F2 NEG12)
{
    double acc = 0.0;
    #pragma unroll
    for (int o = 0; o < 2; o++) {
        F2 facc; facc.v = 0ull;
        #pragma unroll
        for (int k = 0; k < 4; k++) {
            const int lp = lp0 + o * 4 + k;
            F2 xj, yj, zj, qjv, uxj, uyj, uzj;
            xj.v  = sx2[lp];  yj.v  = sy2[lp];  zj.v = sz2[lp]; qjv.v = sq2[lp];
            uxj.v = sux2[lp]; uyj.v = suy2[lp]; uzj.v = suz2[lp];

            F2 dx = add2(xj, nx);
            F2 dy = add2(yj, ny);
            F2 dz = add2(zj, nz);
            F2 rsqp = fma2(dx, dx, fma2(dy, dy, mul2(dz, dz)));

            float r0, r1; unpack2(rsqp, r0, r1);
            if (DIAG) {
                // self pair (r==0) only on diag blocks; made finite, corrected later
                r0 = (r0 == 0.0f) ? 1.0f : r0;
                r1 = (r1 == 0.0f) ? 1.0f : r1;
            }

            float rinv0 = rsqf(r0),        rinv1 = rsqf(r1);
            float g0    = ex2f(r0 * KEXP), g1    = ex2f(r1 * KEXP);
            float e0    = erf_part(r0, rinv0, g0);
            float e1s   = erf_part(r1, rinv1, g1);

            F2 rinvp  = pack2(rinv0, rinv1);
            F2 gaussp = pack2(g0, g1);
            F2 erfp   = pack2(e0, e1s);

            F2 rinv2p = mul2(rinvp, rinvp);
            F2 e1p    = mul2(erfp, rinvp);
            F2 e3p    = mul2(e1p, rinv2p);
            F2 ncgp   = mul2(gaussp, NEGC2);          // -c*gauss
            F2 s1p    = fma2(ncgp, rinv2p, e3p);      // e3 - c*gauss/r^2
            F2 epn    = add2(e3p, ncgp);
            F2 s2p    = fma2(s1p, TWO2, epn);         // 2*s1 + e3 - c*gauss

            F2 udip = fma2(ux, dx, fma2(uy, dy, mul2(uz, dz)));
            F2 udjp = fma2(uxj, dx, fma2(uyj, dy, mul2(uzj, dz)));
            F2 uup  = fma2(ux, uxj, fma2(uy, uyj, mul2(uz, uzj)));

            F2 prp  = mul2(mul2(qjv, qq), e1p);                  // qq
            F2 inn  = fma2(qjv, udip, mul2(nq, udjp));           // qj*udi - qi*udj
            F2 ns1p = mul2(s1p, NEG12);
            prp = fma2(ns1p, inn, prp);                          // qu
            prp = fma2(s1p, uup, prp);                           // uu iso
            F2 m2   = mul2(mul2(udip, udjp), rinv2p);
            F2 ns2p = mul2(s2p, NEG12);
            prp = fma2(ns2p, m2, prp);                           // uu aniso

            facc = add2(facc, prp);
        }
        float f0, f1; unpack2(facc, f0, f1);
        acc += (double)(f0 + f1);
    }
    return acc;
}

__global__ void __launch_bounds__(NT, 4) pair_kernel(
    const float* __restrict__ q, const float* __restrict__ r,
    const float* __restrict__ u, int n, int tiles, float outscale,
    float* __restrict__ out)
{
    // ---- block -> (tile-pair, j-quarter) ----
    int p4 = blockIdx.x;
    int pr = p4 >> 2;
    const int jh = p4 & 3;
    int bi = 0;
    while (pr >= tiles - bi) { pr -= tiles - bi; bi++; }
    const int bj = bi + pr;
    const bool diag = (bi == bj);

    __shared__ __align__(16) float s_x[TJ], s_y[TJ], s_z[TJ], s_q[TJ];
    __shared__ __align__(16) float s_ux[TJ], s_uy[TJ], s_uz[TJ];

    const int tx = threadIdx.x;
    const int il = tx & (TI - 1);     // i-lane 0..127
    const int jg = tx >> 7;           // j-group 0..1 (16 j's each)
    const int i  = bi * TI + il;
    const int j0 = bj * TI + jh * TJ;

    if (tx < TJ) {
        int j = j0 + tx;
        if (j < n) { s_x[tx] = r[3*j]; s_y[tx] = r[3*j+1]; s_z[tx] = r[3*j+2]; s_q[tx] = q[j]; }
        else       { s_x[tx] = 1.0e7f + (float)j; s_y[tx] = 0.f; s_z[tx] = 0.f; s_q[tx] = 0.f; }
    } else if (tx < 2 * TJ) {
        int jt = tx - TJ, j = j0 + jt;
        if (j < n) { s_ux[jt] = u[3*j]; s_uy[jt] = u[3*j+1]; s_uz[jt] = u[3*j+2]; }
        else       { s_ux[jt] = 0.f; s_uy[jt] = 0.f; s_uz[jt] = 0.f; }
    }

    float qi = 0.f, rix, riy = 0.f, riz = 0.f, uix = 0.f, uiy = 0.f, uiz = 0.f;
    if (i < n) {
        qi  = q[i];
        rix = r[3*i]; riy = r[3*i+1]; riz = r[3*i+2];
        uix = u[3*i]; uiy = u[3*i+1]; uiz = u[3*i+2];
    } else {
        rix = 2.0e7f + (float)i;   // far, q=u=0 -> zero contribution
    }
    __syncthreads();

    const F2 nx = pack2(-rix, -rix), ny = pack2(-riy, -riy), nz = pack2(-riz, -riz);
    const F2 ux = pack2(uix, uix),   uy = pack2(uiy, uiy),   uz = pack2(uiz, uiz);
    const F2 qq = pack2(qi, qi),     nq = pack2(-qi, -qi);
    const F2 NEGC2 = pack2(-C_CONST, -C_CONST);
    const F2 TWO2  = pack2(2.0f, 2.0f);
    const F2 NEG12 = pack2(-1.0f, -1.0f);

    const u64* sx2  = reinterpret_cast<const u64*>(s_x);
    const u64* sy2  = reinterpret_cast<const u64*>(s_y);
    const u64* sz2  = reinterpret_cast<const u64*>(s_z);
    const u64* sq2  = reinterpret_cast<const u64*>(s_q);
    const u64* sux2 = reinterpret_cast<const u64*>(s_ux);
    const u64* suy2 = reinterpret_cast<const u64*>(s_uy);
    const u64* suz2 = reinterpret_cast<const u64*>(s_uz);

    const int lp0 = jg * (TJ / 4);    // 8 u64 slots (16 j's) per thread

    double acc;
    if (!diag) {
        acc = block_accum<false>(nx, ny, nz, ux, uy, uz, qq, nq,
                                 sx2, sy2, sz2, sq2, sux2, suy2, suz2,
                                 lp0, NEGC2, TWO2, NEG12);
    } else {
        acc = block_accum<true>(nx, ny, nz, ux, uy, uz, qq, nq,
                                sx2, sy2, sz2, sq2, sux2, suy2, suz2,
                                lp0, NEGC2, TWO2, NEG12);
        // subtract fake self-pair term if i falls in this thread's j-window
        if ((il >> 4) == (jh * 2 + jg))
            acc -= (double)self_term(qi, uix, uiy, uiz);
        acc *= 0.5;   // diagonal tile double-counts each unordered pair
    }

    // ---- deterministic block reduction ----
    #pragma unroll
    for (int off = 16; off > 0; off >>= 1)
        acc += __shfl_down_sync(0xffffffffu, acc, off);

    __shared__ double warp_s[NT / 32];
    if ((tx & 31) == 0) warp_s[tx >> 5] = acc;
    __syncthreads();

    __shared__ bool isLast;
    if (tx == 0) {
        double s = 0.0;
        #pragma unroll
        for (int w = 0; w < NT / 32; w++) s += warp_s[w];
        g_part[blockIdx.x] = s;
        __threadfence();
        unsigned c = atomicAdd(&g_count, 1u);
        isLast = (c == gridDim.x - 1);
    }
    __syncthreads();

    // ---- last block: final reduction (fixed order -> deterministic) ----
    if (isLast) {
        __threadfence();
        const int nB = gridDim.x;
        double s = 0.0;
        for (int k = tx; k < nB; k += NT) s += g_part[k];

        #pragma unroll
        for (int off = 16; off > 0; off >>= 1)
            s += __shfl_down_sync(0xffffffffu, s, off);

        __shared__ double fin_s[NT / 32];
        if ((tx & 31) == 0) fin_s[tx >> 5] = s;
        __syncthreads();
        if (tx == 0) {
            double tot = 0.0;
            #pragma unroll
            for (int w = 0; w < NT / 32; w++) tot += fin_s[w];
            out[0] = (float)(tot * (double)outscale);
            g_count = 0;   // reset for next graph replay
        }
    }
}

extern "C" void kernel_launch(void* const* d_in, const int* in_sizes, int n_in,
                              void* d_out, int out_size)
{
    const float* q = (const float*)d_in[0];
    const float* r = (const float*)d_in[1];
    const float* u = (const float*)d_in[2];
    float* out = (float*)d_out;

    int n = in_sizes[0];
    int tiles = (n + TI - 1) / TI;
    if (tiles > MAX_TILES) tiles = MAX_TILES;

    int nB = tiles * (tiles + 1) * 2;   // 4 j-quarter blocks per triangular tile-pair
    float outscale = (float)(90.0474 / 6.283185307179586476925286766559);

    pair_kernel<<<nB, NT>>>(q, r, u, n, tiles, outscale, out);
}